// round 14
// baseline (speedup 1.0000x reference)
#include <cuda_runtime.h>
#include <cstdint>

#define NUM_CLASSES 32
#define MAX_DET     100
#define CONF        0.25f
#define IOU_C       0.45f
#define HC          1.4901161193847656e-8f   // 2^-26 = half-ulp(0.45f)
#define BATCH       64
#define ANCHORS     8400
#define NT          512
#define KPT         9
#define HALF        (NT * KPT)               // 4608 anchors per CTA
#define PADDED      (2 * HALF)               // 9216
#define NWARPS      (NT / 32)                // 16
#define GROUPW      (32 * KPT)               // 288 anchors per warp-group (32 groups)
#define MAXCAND     8                        // max trusted prefix per pass
#define NEG_INF_I   ((int)0x80000000)
#define IDX_SENT    0x7FFFFFFF

#define P1_NT       512
#define P1_GRIDX    (PADDED / P1_NT)         // 18

// scratch (allocation-free rule: __device__ globals)
__device__ float4 g_box[BATCH * PADDED];
__device__ float  g_sc [BATCH * PADDED];
__device__ float  g_cls[BATCH * PADDED];

// NMS dynamic smem per CTA: FULL float4 boxes[9216] | FULL float cls[9216]
#define SMEM_BYTES (PADDED * 16 + PADDED * 4)

// ---------------- helpers ----------------
__device__ __forceinline__ uint32_t smem_u32(const void* p) {
    uint32_t a;
    asm("{ .reg .u64 t; cvta.to.shared.u64 t, %1; cvt.u32.u64 %0, t; }" : "=r"(a) : "l"(p));
    return a;
}
__device__ __forceinline__ uint32_t mapa_peer(uint32_t laddr, uint32_t peer) {
    uint32_t r;
    asm("mapa.shared::cluster.u32 %0, %1, %2;" : "=r"(r) : "r"(laddr), "r"(peer));
    return r;
}
__device__ __forceinline__ void st_peer_u64(uint32_t raddr, uint64_t v) {
    asm volatile("st.shared::cluster.u64 [%0], %1;" :: "r"(raddr), "l"(v) : "memory");
}
__device__ __forceinline__ void mbar_init(uint32_t a, uint32_t cnt) {
    asm volatile("mbarrier.init.shared.b64 [%0], %1;" :: "r"(a), "r"(cnt) : "memory");
}
__device__ __forceinline__ void mbar_arrive_peer_rel(uint32_t laddr, uint32_t peer) {
    asm volatile("{\n\t.reg .b32 r;\n\t"
                 "mapa.shared::cluster.u32 r, %0, %1;\n\t"
                 "mbarrier.arrive.release.cluster.shared::cluster.b64 _, [r];\n\t}"
                 :: "r"(laddr), "r"(peer) : "memory");
}
__device__ __forceinline__ void mbar_wait_acq(uint32_t a, uint32_t parity) {
    uint32_t done;
    asm volatile("{\n\t.reg .pred p;\n\t"
                 "mbarrier.try_wait.parity.acquire.cluster.shared::cta.b64 p, [%1], %2;\n\t"
                 "selp.b32 %0, 1, 0, p;\n\t}"
                 : "=r"(done) : "r"(a), "r"(parity) : "memory");
    if (!done) {
        asm volatile("{\n\t.reg .pred P1;\n\t"
                     "WL_%=:\n\t"
                     "mbarrier.try_wait.parity.acquire.cluster.shared::cta.b64 P1, [%0], %1;\n\t"
                     "@P1 bra.uni WD_%=;\n\t"
                     "bra.uni WL_%=;\n\t"
                     "WD_%=:\n\t}"
                     :: "r"(a), "r"(parity) : "memory");
    }
}
#define CLUSTER_ARRIVE() asm volatile("barrier.cluster.arrive.aligned;" ::: "memory")
#define CLUSTER_WAIT()   asm volatile("barrier.cluster.wait.aligned;" ::: "memory")

// packed (key, idx): u64 descending order == (key desc, idx asc)
__device__ __forceinline__ uint64_t pack_ki(int k, int i) {
    return ((uint64_t)(uint32_t)(k ^ 0x80000000) << 32) | (uint32_t)(~i);
}
__device__ __forceinline__ int unpack_k(uint64_t e) { return (int)((uint32_t)(e >> 32) ^ 0x80000000u); }
__device__ __forceinline__ int unpack_i(uint64_t e) { return (int)(~(uint32_t)e); }

// exact reference suppression: does winner (wb, wa) suppress box (cb, cab)?
__device__ __forceinline__ bool sup_test(float4 wb, float wa, float4 cb, float cab) {
    float iy1 = fmaxf(wb.x, cb.x);
    float ix1 = fmaxf(wb.y, cb.y);
    float iy2 = fminf(wb.z, cb.z);
    float ix2 = fminf(wb.w, cb.w);
    float inter = fmaxf(iy2 - iy1, 0.0f) * fmaxf(ix2 - ix1, 0.0f);
    float uni = wa + cab - inter;
    float d = fmaf(-IOU_C, uni, inter);
    return d > uni * HC;     // exact fl(inter/uni) > 0.45f
}

// ---------------- Phase 1: full-chip decode ----------------
__global__ __launch_bounds__(P1_NT)
void decode_kernel(const float* __restrict__ in)
{
    const int a = blockIdx.x * P1_NT + threadIdx.x;   // 0..9215
    const int b = blockIdx.y;
    const size_t o = (size_t)b * PADDED + a;

    if (a < ANCHORS) {
        const float* base = in + (size_t)b * (4 + NUM_CLASSES) * ANCHORS;
        float xc = base[0 * ANCHORS + a];
        float yc = base[1 * ANCHORS + a];
        float w  = base[2 * ANCHORS + a];
        float h  = base[3 * ANCHORS + a];

        float bs = base[4 * ANCHORS + a];
        int   bc = 0;
        #pragma unroll
        for (int c = 1; c < NUM_CLASSES; c++) {
            float v = base[(4 + c) * ANCHORS + a];
            if (v > bs) { bs = v; bc = c; }   // strict > = first max (jnp.argmax)
        }

        float hw = w * 0.5f;
        float hh = h * 0.5f;
        float y1 = fminf(fmaxf(yc - hh, 0.0f), 1.0f);
        float x1 = fminf(fmaxf(xc - hw, 0.0f), 1.0f);
        float y2 = fminf(fmaxf(yc + hh, 0.0f), 1.0f);
        float x2 = fminf(fmaxf(xc + hw, 0.0f), 1.0f);

        g_box[o] = make_float4(y1, x1, y2, x2);
        g_sc[o]  = (bs >= CONF) ? bs : -1.0f;
        g_cls[o] = (float)bc;
    } else {
        g_box[o] = make_float4(0.0f, 0.0f, 0.0f, 0.0f);
        g_sc[o]  = -1.0f;
        g_cls[o] = 0.0f;
    }
}

// winner-major suppression accumulation over the register slice.
// CHECK=1 adds the explicit self-index test (only needed for zero-area winners).
#define SCAN_ACCUM(CHECK)                                                      \
    _Pragma("unroll")                                                          \
    for (int t = 0; t < MAXCAND; t++) {                                        \
        if (t < T && ((accmask >> t) & 1)) {                                   \
            float4 W = sbox[ci[t]];                                            \
            float WA = (W.z - W.x) * (W.w - W.y);                              \
            _Pragma("unroll")                                                  \
            for (int k = 0; k < KPT; k++) {                                    \
                float ab = (ry2[k] - ry1[k]) * (rx2[k] - rx1[k]);              \
                float q1 = fmaxf(W.x, ry1[k]);                                 \
                float q2 = fmaxf(W.y, rx1[k]);                                 \
                float q3 = fminf(W.z, ry2[k]);                                 \
                float q4 = fminf(W.w, rx2[k]);                                 \
                float it = fmaxf(q3 - q1, 0.0f) * fmaxf(q4 - q2, 0.0f);        \
                float u  = WA + ab - it;                                       \
                float e  = fmaf(-IOU_C, u, it);                                \
                bool s = (e > u * HC);                                         \
                if (CHECK) s = s || (gbase + k == ci[t]);                      \
                sup[k] = sup[k] || s;                                          \
            }                                                                  \
        }                                                                      \
    }

// ---------------- Phase 2: 2-CTA-cluster NMS, trusted-prefix multi-emit ----------------
__global__ __launch_bounds__(NT, 1) __cluster_dims__(2, 1, 1)
void nms_kernel(float* __restrict__ out)
{
    extern __shared__ char smem[];
    float4* sbox = reinterpret_cast<float4*>(smem);                 // FULL boxes
    float*  scls = reinterpret_cast<float*>(smem + PADDED * 16);    // FULL classes

    __shared__ __align__(16) uint64_t s_own [2][2 * NWARPS];  // own warp top-2 (32)
    __shared__ __align__(16) uint64_t s_mail[2][2 * NWARPS];  // peer warp top-2 (32)
    __shared__ uint64_t s_mbar[2];

    const int tid  = threadIdx.x;
    const int lane = tid & 31;
    const int wid  = tid >> 5;
    const unsigned FULL = 0xffffffffu;
    uint32_t rank;
    asm("mov.u32 %0, %%cluster_ctarank;" : "=r"(rank));
    const uint32_t peer = rank ^ 1;
    const int b = blockIdx.x >> 1;

    const uint32_t mb0 = smem_u32(&s_mbar[0]);
    const uint32_t mb1 = smem_u32(&s_mbar[1]);
    const uint32_t pm0 = mapa_peer(smem_u32(&s_mail[0][0]), peer);
    const uint32_t pm1 = mapa_peer(smem_u32(&s_mail[1][0]), peer);

    if (tid == 0) { mbar_init(mb0, NWARPS); mbar_init(mb1, NWARPS); }

    // coalesced fill of the FULL arrays (both CTAs replicate)
    const float4* gb = g_box + (size_t)b * PADDED;
    const float*  gc = g_cls + (size_t)b * PADDED;
    for (int a = tid; a < PADDED; a += NT) { sbox[a] = gb[a]; scls[a] = gc[a]; }
    __syncthreads();

    CLUSTER_ARRIVE(); CLUSTER_WAIT();        // mbarrier init visible cluster-wide

    // register slice: this CTA owns global anchors [rank*HALF + t*9, +9)
    float ry1[KPT], rx1[KPT], ry2[KPT], rx2[KPT], rsc[KPT];
    const int gbase = (int)rank * HALF + tid * KPT;
    const float* gs = g_sc + (size_t)b * PADDED + gbase;
    int tk1 = NEG_INF_I, ti1 = 0, tk2 = NEG_INF_I, ti2 = 0;
    #pragma unroll
    for (int k = 0; k < KPT; k++) {
        float4 v = sbox[gbase + k];
        ry1[k] = v.x; rx1[k] = v.y; ry2[k] = v.z; rx2[k] = v.w;
        float sv = gs[k];
        rsc[k] = sv;
        int ik = __float_as_int(sv);
        if (ik > tk1)      { tk2 = tk1; ti2 = ti1; tk1 = ik; ti1 = gbase + k; }
        else if (ik > tk2) { tk2 = ik; ti2 = gbase + k; }
    }

    float* out_boxes = out + (size_t)b * MAX_DET * 4;
    float* out_cls   = out + (size_t)BATCH * MAX_DET * 4 + (size_t)b * MAX_DET;
    float* out_sc    = out + (size_t)BATCH * MAX_DET * 5 + (size_t)b * MAX_DET;
    float* out_nd    = out + (size_t)BATCH * MAX_DET * 6 + b;

    const uint64_t SENTMIN = pack_ki(NEG_INF_I, IDX_SENT);

    int ndet = 0, p = 0, ph0 = 0, ph1 = 0;
    while (ndet < MAX_DET) {
        // ---- Stage B: warp top-2 via redux.max + redux.min-on-index ----
        int m1 = __reduce_max_sync(FULL, tk1);
        int I1 = __reduce_min_sync(FULL, (tk1 == m1) ? ti1 : IDX_SENT);
        bool win = (ti1 == I1);               // anchor idx unique -> one lane
        int kx = win ? tk2 : tk1;
        int ix = win ? ti2 : ti1;
        int m2 = __reduce_max_sync(FULL, kx);
        int I2 = __reduce_min_sync(FULL, (kx == m2) ? ix : IDX_SENT);

        // ---- publish warp entries: own smem + peer smem (DSMEM), arrive ----
        // Parity double-buffer: rewriting buffers of parity p at pass t is safe
        // since our pass t-1 wait on mbar[p^1] required all peer arrives, each
        // program-ordered after that warp's pass t-2 reads of parity-p data.
        uint32_t mb = p ? mb1 : mb0;
        if (lane == 0) {
            uint64_t e1p = pack_ki(m1, I1);
            uint64_t e2p = pack_ki(m2, I2);
            s_own[p][2 * wid]     = e1p;
            s_own[p][2 * wid + 1] = e2p;
            uint32_t r = (p ? pm1 : pm0) + (uint32_t)(wid * 16);
            st_peer_u64(r,     e1p);
            st_peer_u64(r + 8, e2p);
            mbar_arrive_peer_rel(mb, peer);   // release: orders the two stores
        }
        __syncthreads();                       // own entries visible CTA-wide
        mbar_wait_acq(mb, (uint32_t)(p ? ph1 : ph0));   // all 16 peer arrives
        if (p) ph1 ^= 1; else ph0 ^= 1;

        // ---- Stage C: extract the trusted prefix of the 64-entry multiset ----
        // Multiset = per-warp-group top-2. The merged desc order is the exact
        // global order up to AND INCLUDING the first entry that is its group's
        // second contribution (beyond that, the group's #3 could be missing).
        uint64_t ea = s_own [p][lane];
        uint64_t eb = s_mail[p][lane];
        uint64_t hi = (ea > eb) ? ea : eb;
        uint64_t lo = (ea > eb) ? eb : ea;
        int ck[MAXCAND], ci[MAXCAND];
        int T = 0;
        unsigned gmask = 0;
        bool stop = false;
        #pragma unroll
        for (int t = 0; t < MAXCAND; t++) {
            ck[t] = NEG_INF_I; ci[t] = 0;
            if (!stop) {                      // uniform across cluster
                int k = unpack_k(hi); int i = unpack_i(hi);
                int M = __reduce_max_sync(FULL, k);
                int I = __reduce_min_sync(FULL, (k == M) ? i : IDX_SENT);
                if (M <= 0) {
                    stop = true;              // no live entries left
                } else {
                    ck[t] = M; ci[t] = I; T = t + 1;
                    if (k == M && i == I) { hi = lo; lo = SENTMIN; }   // pop
                    unsigned bit = 1u << (I / GROUPW);
                    if (gmask & bit) stop = true;   // group's 2nd: trusted, stop after
                    else gmask |= bit;
                }
            }
        }
        if (T == 0) break;                    // symmetric data -> uniform break

        // ---- acceptance chain over the trusted prefix (exact sorted-scan NMS) ----
        // Candidate t is the reference's next winner iff it survives sup_test vs
        // every ACCEPTED predecessor (suppressed candidates never suppress).
        int budget = MAX_DET - ndet;          // >= 1
        unsigned accmask = 0;
        int na = 0;
        bool allpos = true;
        #pragma unroll
        for (int t = 0; t < MAXCAND; t++) {
            if (t < T) {
                float4 cbt = sbox[ci[t]];
                float cat = (cbt.z - cbt.x) * (cbt.w - cbt.y);
                bool dead = false;
                #pragma unroll
                for (int u = 0; u < MAXCAND; u++) {
                    if (u < t) {
                        if ((accmask >> u) & 1) {
                            float4 cbu = sbox[ci[u]];
                            float cau = (cbu.z - cbu.x) * (cbu.w - cbu.y);
                            dead = dead || sup_test(cbu, cau, cbt, cat);
                        }
                    }
                }
                if (!dead && na < budget) {
                    accmask |= 1u << t;
                    na++;
                    allpos = allpos && (cat > 0.0f);
                }
            }
        }

        // ---- emit accepted candidates in order ----
        if (rank == 0 && tid == 0) {
            int q = ndet;
            #pragma unroll
            for (int t = 0; t < MAXCAND; t++) {
                if (t < T && ((accmask >> t) & 1)) {
                    *reinterpret_cast<float4*>(out_boxes + q * 4) = sbox[ci[t]];
                    out_cls[q] = scls[ci[t]];
                    out_sc[q]  = __int_as_float(ck[t]);
                    q++;
                }
            }
        }

        ndet += na;

        // ---- register scan: suppress vs accepted winners + fresh top-2 ----
        // Fast path: positive-area winners self-suppress via their own IoU test
        // (in == ab == aa exactly => e = 0.55*aa > aa*2^-26), so no index checks.
        if (ndet < MAX_DET && tk1 > 0) {      // dead slice -> state stays exact
            bool sup[KPT];
            #pragma unroll
            for (int k = 0; k < KPT; k++) sup[k] = false;
            if (allpos) { SCAN_ACCUM(0) } else { SCAN_ACCUM(1) }
            int nk1 = NEG_INF_I, ni1 = 0, nk2 = NEG_INF_I, ni2 = 0;
            #pragma unroll
            for (int k = 0; k < KPT; k++) {
                float v = sup[k] ? -1.0f : rsc[k];
                rsc[k] = v;
                int ik = __float_as_int(v);
                if (ik > nk1)      { nk2 = nk1; ni2 = ni1; nk1 = ik; ni1 = gbase + k; }
                else if (ik > nk2) { nk2 = ik; ni2 = gbase + k; }
            }
            tk1 = nk1; ti1 = ni1; tk2 = nk2; ti2 = ni2;
        }

        p ^= 1;
    }

    // tail zero-fill (out is poisoned; reference emits zeros for !ok slots)
    if (rank == 0) {
        for (int i = ndet + tid; i < MAX_DET; i += NT) {
            out_boxes[i * 4 + 0] = 0.0f;
            out_boxes[i * 4 + 1] = 0.0f;
            out_boxes[i * 4 + 2] = 0.0f;
            out_boxes[i * 4 + 3] = 0.0f;
            out_cls[i] = 0.0f;
            out_sc[i]  = 0.0f;
        }
        if (tid == 0) *out_nd = (float)ndet;
    }

    CLUSTER_ARRIVE(); CLUSTER_WAIT();    // no CTA exits while peer may signal it
}

extern "C" void kernel_launch(void* const* d_in, const int* in_sizes, int n_in,
                              void* d_out, int out_size)
{
    (void)in_sizes; (void)n_in; (void)out_size;
    const float* in = (const float*)d_in[0];
    float* out = (float*)d_out;

    cudaFuncSetAttribute(nms_kernel,
                         cudaFuncAttributeMaxDynamicSharedMemorySize, SMEM_BYTES);

    dim3 g1(P1_GRIDX, BATCH);
    decode_kernel<<<g1, P1_NT>>>(in);
    nms_kernel<<<2 * BATCH, NT, SMEM_BYTES>>>(out);
}